// round 7
// baseline (speedup 1.0000x reference)
#include <cuda_runtime.h>

// TriMipEncoding: x [N,3] in [0,1], fm [3,512,512,16] fp32. out [N,48].
//
// R7 = R6 with 4 independent units per thread (MLP 16 front-batched).
// Thread handles (idx + k*q), k=0..3, q = n_pts*3. Straight-line decode,
// 16 LDG.128 batched, then blend+store. evict_last on fm, streaming stores.

#define PLANE_H 512
#define PLANE_W 512

__device__ __forceinline__ float4 ldg_resident(const float4* p, unsigned long long pol) {
    float4 v;
    asm("ld.global.nc.L2::cache_hint.v4.f32 {%0,%1,%2,%3}, [%4], %5;"
        : "=f"(v.x), "=f"(v.y), "=f"(v.z), "=f"(v.w)
        : "l"(p), "l"(pol));
    return v;
}

struct Unit {
    const float4* a00; const float4* a01; const float4* a10; const float4* a11;
    float w00, w01, w10, w11;
};

__device__ __forceinline__ Unit decode(int idx, const float* __restrict__ x,
                                        const float4* __restrict__ fm4) {
    Unit un;
    int c = idx & 3;
    int t = idx >> 2;
    int n = t / 3;           // magic-mul
    int p = t - n * 3;

    float x0 = __ldg(x + n * 3 + 0);
    float x1 = __ldg(x + n * 3 + 1);
    float x2 = __ldg(x + n * 3 + 2);

    float cu = (p == 0) ? x1 : x0;
    float cv = (p == 2) ? x1 : x2;

    float u = cu * (float)PLANE_W - 0.5f;
    float v = cv * (float)PLANE_H - 0.5f;
    float i0f = floorf(u);
    float j0f = floorf(v);
    float fu = u - i0f;
    float fv = v - j0f;

    int i0 = min(max((int)i0f,     0), PLANE_W - 1);
    int i1 = min(max((int)i0f + 1, 0), PLANE_W - 1);
    int j0 = min(max((int)j0f,     0), PLANE_H - 1);
    int j1 = min(max((int)j0f + 1, 0), PLANE_H - 1);

    un.w00 = (1.0f - fv) * (1.0f - fu);
    un.w01 = (1.0f - fv) * fu;
    un.w10 = fv * (1.0f - fu);
    un.w11 = fv * fu;

    size_t plane_base = (size_t)p * PLANE_H * PLANE_W * 4 + c;
    size_t r0 = plane_base + (size_t)j0 * (PLANE_W * 4);
    size_t r1 = plane_base + (size_t)j1 * (PLANE_W * 4);
    un.a00 = fm4 + r0 + (size_t)i0 * 4;
    un.a01 = fm4 + r0 + (size_t)i1 * 4;
    un.a10 = fm4 + r1 + (size_t)i0 * 4;
    un.a11 = fm4 + r1 + (size_t)i1 * 4;
    return un;
}

__device__ __forceinline__ float4 blend(const Unit& un,
                                        float4 a, float4 b, float4 d, float4 e) {
    float4 r;
    r.x = un.w00 * a.x + un.w01 * b.x + un.w10 * d.x + un.w11 * e.x;
    r.y = un.w00 * a.y + un.w01 * b.y + un.w10 * d.y + un.w11 * e.y;
    r.z = un.w00 * a.z + un.w01 * b.z + un.w10 * d.z + un.w11 * e.z;
    r.w = un.w00 * a.w + un.w01 * b.w + un.w10 * d.w + un.w11 * e.w;
    return r;
}

__global__ void __launch_bounds__(128) trimip_kernel(
    const float* __restrict__ x,
    const float4* __restrict__ fm4,
    float4* __restrict__ out4,
    int q)   // = n_pts * 3 ; units at idx + k*q, k=0..3
{
    int idx = blockIdx.x * blockDim.x + threadIdx.x;
    if (idx >= q) return;

    unsigned long long pol;
    asm("createpolicy.fractional.L2::evict_last.b64 %0, 1.0;" : "=l"(pol));

    Unit u0 = decode(idx,         x, fm4);
    Unit u1 = decode(idx + q,     x, fm4);
    Unit u2 = decode(idx + 2 * q, x, fm4);
    Unit u3 = decode(idx + 3 * q, x, fm4);

    // Front-batch all 16 gathers (MLP = 16)
    float4 a0 = ldg_resident(u0.a00, pol);
    float4 b0 = ldg_resident(u0.a01, pol);
    float4 d0 = ldg_resident(u0.a10, pol);
    float4 e0 = ldg_resident(u0.a11, pol);
    float4 a1 = ldg_resident(u1.a00, pol);
    float4 b1 = ldg_resident(u1.a01, pol);
    float4 d1 = ldg_resident(u1.a10, pol);
    float4 e1 = ldg_resident(u1.a11, pol);
    float4 a2 = ldg_resident(u2.a00, pol);
    float4 b2 = ldg_resident(u2.a01, pol);
    float4 d2 = ldg_resident(u2.a10, pol);
    float4 e2 = ldg_resident(u2.a11, pol);
    float4 a3 = ldg_resident(u3.a00, pol);
    float4 b3 = ldg_resident(u3.a01, pol);
    float4 d3 = ldg_resident(u3.a10, pol);
    float4 e3 = ldg_resident(u3.a11, pol);

    __stcs(out4 + idx,         blend(u0, a0, b0, d0, e0));
    __stcs(out4 + idx + q,     blend(u1, a1, b1, d1, e1));
    __stcs(out4 + idx + 2 * q, blend(u2, a2, b2, d2, e2));
    __stcs(out4 + idx + 3 * q, blend(u3, a3, b3, d3, e3));
}

extern "C" void kernel_launch(void* const* d_in, const int* in_sizes, int n_in,
                              void* d_out, int out_size)
{
    const float*  x   = (const float*)d_in[0];    // [N,3]
    const float4* fm4 = (const float4*)d_in[1];   // [3,512,512,16] as float4
    float4* out4 = (float4*)d_out;                // [N,48] as float4

    int n_pts = in_sizes[0] / 3;
    int q = n_pts * 3;                             // n_pts*12 / 4
    int threads = 128;
    int blocks = (q + threads - 1) / threads;
    trimip_kernel<<<blocks, threads>>>(x, fm4, out4, q);
}

// round 8
// speedup vs baseline: 1.0054x; 1.0054x over previous
#include <cuda_runtime.h>

// TriMipEncoding: x [N,3] in [0,1], fm [3,512,512,16] fp32. out [N,48].
//
// R8 = R6 structure, 3 units/thread, with asm VOLATILE gathers so ptxas
// cannot re-serialize the load batch (R7 showed regs=32 -> ptxas defeated
// the 16-load batch). Volatile ordering forces all 12 LDG.128 issued
// back-to-back with 48 live data regs -> true MLP 12/warp.

#define PLANE_H 512
#define PLANE_W 512

__device__ __forceinline__ float4 ldg_resident_v(const float4* p, unsigned long long pol) {
    float4 v;
    asm volatile("ld.global.nc.L2::cache_hint.v4.f32 {%0,%1,%2,%3}, [%4], %5;"
        : "=f"(v.x), "=f"(v.y), "=f"(v.z), "=f"(v.w)
        : "l"(p), "l"(pol));
    return v;
}

struct Unit {
    const float4* a00; const float4* a01; const float4* a10; const float4* a11;
    float w00, w01, w10, w11;
};

__device__ __forceinline__ Unit decode(int idx, const float* __restrict__ x,
                                        const float4* __restrict__ fm4) {
    Unit un;
    int c = idx & 3;
    int t = idx >> 2;
    int n = t / 3;           // magic-mul
    int p = t - n * 3;

    float x0 = __ldg(x + n * 3 + 0);
    float x1 = __ldg(x + n * 3 + 1);
    float x2 = __ldg(x + n * 3 + 2);

    float cu = (p == 0) ? x1 : x0;
    float cv = (p == 2) ? x1 : x2;

    float u = cu * (float)PLANE_W - 0.5f;
    float v = cv * (float)PLANE_H - 0.5f;
    float i0f = floorf(u);
    float j0f = floorf(v);
    float fu = u - i0f;
    float fv = v - j0f;

    int i0 = min(max((int)i0f,     0), PLANE_W - 1);
    int i1 = min(max((int)i0f + 1, 0), PLANE_W - 1);
    int j0 = min(max((int)j0f,     0), PLANE_H - 1);
    int j1 = min(max((int)j0f + 1, 0), PLANE_H - 1);

    un.w00 = (1.0f - fv) * (1.0f - fu);
    un.w01 = (1.0f - fv) * fu;
    un.w10 = fv * (1.0f - fu);
    un.w11 = fv * fu;

    size_t plane_base = (size_t)p * PLANE_H * PLANE_W * 4 + c;
    size_t r0 = plane_base + (size_t)j0 * (PLANE_W * 4);
    size_t r1 = plane_base + (size_t)j1 * (PLANE_W * 4);
    un.a00 = fm4 + r0 + (size_t)i0 * 4;
    un.a01 = fm4 + r0 + (size_t)i1 * 4;
    un.a10 = fm4 + r1 + (size_t)i0 * 4;
    un.a11 = fm4 + r1 + (size_t)i1 * 4;
    return un;
}

__device__ __forceinline__ float4 blend(const Unit& un,
                                        float4 a, float4 b, float4 d, float4 e) {
    float4 r;
    r.x = un.w00 * a.x + un.w01 * b.x + un.w10 * d.x + un.w11 * e.x;
    r.y = un.w00 * a.y + un.w01 * b.y + un.w10 * d.y + un.w11 * e.y;
    r.z = un.w00 * a.z + un.w01 * b.z + un.w10 * d.z + un.w11 * e.z;
    r.w = un.w00 * a.w + un.w01 * b.w + un.w10 * d.w + un.w11 * e.w;
    return r;
}

__global__ void __launch_bounds__(128) trimip_kernel(
    const float* __restrict__ x,
    const float4* __restrict__ fm4,
    float4* __restrict__ out4,
    int q)   // = n_pts * 4 ; units at idx + k*q, k=0..2
{
    int idx = blockIdx.x * blockDim.x + threadIdx.x;
    if (idx >= q) return;

    unsigned long long pol;
    asm("createpolicy.fractional.L2::evict_last.b64 %0, 1.0;" : "=l"(pol));

    Unit u0 = decode(idx,         x, fm4);
    Unit u1 = decode(idx + q,     x, fm4);
    Unit u2 = decode(idx + 2 * q, x, fm4);

    // 12 volatile gathers: ptxas must issue back-to-back, 48 live data regs.
    float4 a0 = ldg_resident_v(u0.a00, pol);
    float4 b0 = ldg_resident_v(u0.a01, pol);
    float4 d0 = ldg_resident_v(u0.a10, pol);
    float4 e0 = ldg_resident_v(u0.a11, pol);
    float4 a1 = ldg_resident_v(u1.a00, pol);
    float4 b1 = ldg_resident_v(u1.a01, pol);
    float4 d1 = ldg_resident_v(u1.a10, pol);
    float4 e1 = ldg_resident_v(u1.a11, pol);
    float4 a2 = ldg_resident_v(u2.a00, pol);
    float4 b2 = ldg_resident_v(u2.a01, pol);
    float4 d2 = ldg_resident_v(u2.a10, pol);
    float4 e2 = ldg_resident_v(u2.a11, pol);

    __stcs(out4 + idx,         blend(u0, a0, b0, d0, e0));
    __stcs(out4 + idx + q,     blend(u1, a1, b1, d1, e1));
    __stcs(out4 + idx + 2 * q, blend(u2, a2, b2, d2, e2));
}

extern "C" void kernel_launch(void* const* d_in, const int* in_sizes, int n_in,
                              void* d_out, int out_size)
{
    const float*  x   = (const float*)d_in[0];    // [N,3]
    const float4* fm4 = (const float4*)d_in[1];   // [3,512,512,16] as float4
    float4* out4 = (float4*)d_out;                // [N,48] as float4

    int n_pts = in_sizes[0] / 3;
    int q = n_pts * 4;                             // n_pts*12 / 3
    int threads = 128;
    int blocks = (q + threads - 1) / threads;
    trimip_kernel<<<blocks, threads>>>(x, fm4, out4, q);
}